// round 2
// baseline (speedup 1.0000x reference)
#include <cuda_runtime.h>
#include <stdint.h>
#include <stddef.h>

#define BB 256
#define TT 512
#define HH 128
#define GG 384   /* 3*H */

typedef unsigned long long ull;

// ---------------- scratch (device globals; no allocation allowed) ----------
__device__ float g_xw0f[(size_t)BB * TT * GG];
__device__ float g_xw0b[(size_t)BB * TT * GG];
__device__ float g_h0  [(size_t)BB * TT * 2 * HH];
__device__ float g_xw1f[(size_t)BB * TT * GG];
__device__ float g_h1f [BB * HH];

// ---------------- packed f32x2 helpers -------------------------------------
__device__ __forceinline__ void ffma2(ull &d, ull a, ull b) {
    asm("fma.rn.f32x2 %0, %1, %2, %0;" : "+l"(d) : "l"(a), "l"(b));
}
__device__ __forceinline__ float hsum2(ull v) {
    float lo, hi;
    asm("mov.b64 {%0,%1}, %2;" : "=f"(lo), "=f"(hi) : "l"(v));
    return lo + hi;
}
__device__ __forceinline__ float sigf(float x)     { return 1.f / (1.f + __expf(-x)); }
__device__ __forceinline__ float tanhfast(float x) { return 2.f / (1.f + __expf(-2.f * x)) - 1.f; }

// ---------------- GEMM: C[M,384] = A[M,K] @ W[384,K]^T + bias --------------
// BM=BN=64, 256 threads, 4x4 micro-tile (stride 16), K-packed FFMA2.
// Panels stored row-major with LD=K+4 pad: lane stride 1040B == 16 mod 128
// -> conflict-free LDS.128, 16B aligned.
template <int K>
__global__ void __launch_bounds__(256) gemm_xw(const float* __restrict__ A,
                                               const float* __restrict__ W,
                                               const float* __restrict__ bias,
                                               float* __restrict__ C) {
    constexpr int LD = K + 4;
    extern __shared__ float sm[];
    float* As = sm;              // [64][LD]
    float* Ws = sm + 64 * LD;    // [64][LD]
    const int tid = threadIdx.x;
    const int n0 = blockIdx.x * 64;   // 6 n-tiles
    const int m0 = blockIdx.y * 64;   // 2048 m-tiles

    #pragma unroll
    for (int i = tid; i < 64 * (K / 4); i += 256) {
        int kc = i % (K / 4), m = i / (K / 4);
        *reinterpret_cast<float4*>(&As[m * LD + 4 * kc]) =
            *reinterpret_cast<const float4*>(&A[(size_t)(m0 + m) * K + 4 * kc]);
    }
    #pragma unroll
    for (int i = tid; i < 64 * (K / 4); i += 256) {
        int kc = i % (K / 4), n = i / (K / 4);
        *reinterpret_cast<float4*>(&Ws[n * LD + 4 * kc]) =
            *reinterpret_cast<const float4*>(&W[(size_t)(n0 + n) * K + 4 * kc]);
    }
    __syncthreads();

    const int tx = tid & 15, ty = tid >> 4;
    ull acc[4][4];
    #pragma unroll
    for (int i = 0; i < 4; i++)
        #pragma unroll
        for (int j = 0; j < 4; j++) acc[i][j] = 0ULL;

    #pragma unroll 4
    for (int kc = 0; kc < K / 4; ++kc) {
        ulonglong2 av[4], wv[4];
        #pragma unroll
        for (int i = 0; i < 4; i++)
            av[i] = *reinterpret_cast<const ulonglong2*>(&As[(ty + 16 * i) * LD + 4 * kc]);
        #pragma unroll
        for (int j = 0; j < 4; j++)
            wv[j] = *reinterpret_cast<const ulonglong2*>(&Ws[(tx + 16 * j) * LD + 4 * kc]);
        #pragma unroll
        for (int i = 0; i < 4; i++)
            #pragma unroll
            for (int j = 0; j < 4; j++) {
                ffma2(acc[i][j], av[i].x, wv[j].x);
                ffma2(acc[i][j], av[i].y, wv[j].y);
            }
    }

    #pragma unroll
    for (int i = 0; i < 4; i++) {
        int m = m0 + ty + 16 * i;
        #pragma unroll
        for (int j = 0; j < 4; j++) {
            int n = n0 + tx + 16 * j;
            C[(size_t)m * GG + n] = hsum2(acc[i][j]) + bias[n];
        }
    }
}

// ---------------- GRU scan -------------------------------------------------
// Block = R batch rows of one direction, 32*R*KSPLIT threads (8 warps).
// warp w -> (row m = w%R, k-slice ks = w/R). Lane l owns units {l+32q}.
// Whh resident in smem, natural [384][128] layout padded to 132 (row stride
// 528B == 16 mod 128 -> conflict-free LDS.128). K-packed FFMA2 accumulators.
// Non-zero ks warps dump partials to smem; ks==0 warps reduce + activations.
template <int R, int KSPLIT, bool STORE_SEQ>
__global__ void __launch_bounds__(32 * R * KSPLIT) gru_scan(
    const float* __restrict__ xw_f, const float* __restrict__ xw_b,
    const float* __restrict__ Whh_f, const float* __restrict__ Whh_b,
    const float* __restrict__ bhh_f, const float* __restrict__ bhh_b,
    float* __restrict__ out_seq,     // [B,T,2H], column offset dir*H  (STORE_SEQ)
    float* __restrict__ out_final)   // [B,H]                          (!STORE_SEQ)
{
    constexpr int NT  = 32 * R * KSPLIT;
    constexpr int KL  = HH / KSPLIT;
    constexpr int WLD = HH + 4;   // 132
    extern __shared__ float sm[];
    float* wsm = sm;                   // [384][132]
    float* hsm = wsm + GG * WLD;       // [R][128]
    float* psm = hsm + R * HH;         // [KSPLIT-1][R][384]

    const int tid = threadIdx.x;
    const int w = tid >> 5, l = tid & 31;
    const int m = w % R, ks = w / R;
    const int dir = blockIdx.y;
    const int b = blockIdx.x * R + m;

    const float* xw  = dir ? xw_b  : xw_f;
    const float* Whh = dir ? Whh_b : Whh_f;
    const float* bhh = dir ? bhh_b : bhh_f;

    // weights: coalesced global read, conflict-free smem store
    for (int i = tid; i < GG * HH; i += NT) {
        int row = i >> 7, k = i & 127;
        wsm[row * WLD + k] = Whh[i];
    }
    for (int i = tid; i < R * HH; i += NT) hsm[i] = 0.f;
    __syncthreads();

    const int k0 = ks * KL;
    float bR[4], bZ[4], bN[4];
    #pragma unroll
    for (int q = 0; q < 4; q++) {
        int u = l + 32 * q;
        bR[q] = bhh[u]; bZ[q] = bhh[128 + u]; bN[q] = bhh[256 + u];
    }

    float xc[3][4], xn[3][4];
    if (ks == 0) {
        const int t0 = dir ? TT - 1 : 0;
        const float* p = xw + ((size_t)b * TT + t0) * GG;
        #pragma unroll
        for (int g = 0; g < 3; g++)
            #pragma unroll
            for (int q = 0; q < 4; q++) xc[g][q] = p[g * 128 + l + 32 * q];
    }

    const float* hrow = hsm + m * HH;
    const float* wbase = wsm + l * WLD + k0;

    for (int it = 0; it < TT; ++it) {
        const int t = dir ? (TT - 1 - it) : it;
        if (ks == 0 && it + 1 < TT) {
            const int tn = dir ? (TT - 2 - it) : (it + 1);
            const float* p = xw + ((size_t)b * TT + tn) * GG;
            #pragma unroll
            for (int g = 0; g < 3; g++)
                #pragma unroll
                for (int q = 0; q < 4; q++) xn[g][q] = p[g * 128 + l + 32 * q];
        }

        ull acc[3][4];
        #pragma unroll
        for (int g = 0; g < 3; g++)
            #pragma unroll
            for (int q = 0; q < 4; q++) acc[g][q] = 0ULL;

        #pragma unroll
        for (int kk = 0; kk < KL; kk += 4) {
            ulonglong2 hv = *reinterpret_cast<const ulonglong2*>(&hrow[k0 + kk]);
            #pragma unroll
            for (int g = 0; g < 3; g++)
                #pragma unroll
                for (int q = 0; q < 4; q++) {
                    ulonglong2 wv = *reinterpret_cast<const ulonglong2*>(
                        &wbase[(g * 128 + 32 * q) * WLD + kk]);
                    ffma2(acc[g][q], wv.x, hv.x);
                    ffma2(acc[g][q], wv.y, hv.y);
                }
        }

        if (ks > 0) {
            float* pp = psm + ((size_t)(ks - 1) * R + m) * GG;
            #pragma unroll
            for (int g = 0; g < 3; g++)
                #pragma unroll
                for (int q = 0; q < 4; q++)
                    pp[g * 128 + l + 32 * q] = hsum2(acc[g][q]);
        }
        __syncthreads();

        if (ks == 0) {
            #pragma unroll
            for (int q = 0; q < 4; q++) {
                const int u = l + 32 * q;
                float aR = hsum2(acc[0][q]);
                float aZ = hsum2(acc[1][q]);
                float aN = hsum2(acc[2][q]);
                #pragma unroll
                for (int s = 1; s < KSPLIT; ++s) {
                    const float* pp = psm + ((size_t)(s - 1) * R + m) * GG;
                    aR += pp[u]; aZ += pp[128 + u]; aN += pp[256 + u];
                }
                float r = sigf(xc[0][q] + aR + bR[q]);
                float z = sigf(xc[1][q] + aZ + bZ[q]);
                float n = tanhfast(xc[2][q] + r * (aN + bN[q]));
                float ho = hrow[u];
                float hn = n + z * (ho - n);
                hsm[m * HH + u] = hn;
                if (STORE_SEQ)
                    out_seq[((size_t)b * TT + t) * (2 * HH) + dir * HH + u] = hn;
            }
            #pragma unroll
            for (int g = 0; g < 3; g++)
                #pragma unroll
                for (int q = 0; q < 4; q++) xc[g][q] = xn[g][q];
        }
        __syncthreads();
    }

    if (!STORE_SEQ && ks == 0) {
        #pragma unroll
        for (int q = 0; q < 4; q++)
            out_final[b * HH + l + 32 * q] = hsm[m * HH + l + 32 * q];
    }
}

// ---------------- epilogue: layer-1 backward first step + ReLU + FC --------
// K-packed FFMA2 straight from Wih1b's natural [384][256] layout (L2-hot).
__global__ void __launch_bounds__(128) final_kernel(
    const float* __restrict__ h0,     // [B,T,256] layer-0 concat
    const float* __restrict__ h1f,    // [B,128]   layer-1 fwd final state
    const float* __restrict__ Wih1b,  // [384][256]
    const float* __restrict__ bih, const float* __restrict__ bhh,
    const float* __restrict__ fc_w, const float* __restrict__ fc_b,
    float* __restrict__ out)          // [B,2]
{
    const int b = blockIdx.x, j = threadIdx.x;
    __shared__ __align__(16) float x1[256];
    __shared__ float red[2][128];

    const float* src = h0 + ((size_t)b * TT + (TT - 1)) * 256;
    x1[j] = src[j];
    x1[j + 128] = src[j + 128];
    __syncthreads();

    ull acc[3] = {0ULL, 0ULL, 0ULL};
    #pragma unroll 4
    for (int k = 0; k < 256; k += 4) {
        ulonglong2 xv = *reinterpret_cast<const ulonglong2*>(&x1[k]);
        #pragma unroll
        for (int g = 0; g < 3; g++) {
            ulonglong2 wv = *reinterpret_cast<const ulonglong2*>(
                &Wih1b[(size_t)(g * 128 + j) * 256 + k]);
            ffma2(acc[g], wv.x, xv.x);
            ffma2(acc[g], wv.y, xv.y);
        }
    }
    float a0 = hsum2(acc[0]) + bih[j];
    float a1 = hsum2(acc[1]) + bih[j + 128];
    float a2 = hsum2(acc[2]) + bih[j + 256];

    // reverse-scan first step at t=T-1 with h_prev = 0
    float r = sigf(a0 + bhh[j]);
    float z = sigf(a1 + bhh[j + 128]);
    float n = tanhfast(a2 + r * bhh[j + 256]);
    float hbv = (1.f - z) * n;

    float af = fmaxf(h1f[b * HH + j], 0.f);
    float ab = fmaxf(hbv, 0.f);
    red[0][j] = af * fc_w[j]       + ab * fc_w[128 + j];
    red[1][j] = af * fc_w[256 + j] + ab * fc_w[256 + 128 + j];
    __syncthreads();
    for (int s = 64; s > 0; s >>= 1) {
        if (j < s) { red[0][j] += red[0][j + s]; red[1][j] += red[1][j + s]; }
        __syncthreads();
    }
    if (j < 2) out[b * 2 + j] = red[j][0] + fc_b[j];
}

// ---------------- launch ----------------------------------------------------
extern "C" void kernel_launch(void* const* d_in, const int* in_sizes, int n_in,
                              void* d_out, int out_size) {
    const float* x     = (const float*)d_in[0];
    const float* Wih0f = (const float*)d_in[1];
    const float* Whh0f = (const float*)d_in[2];
    const float* bih0f = (const float*)d_in[3];
    const float* bhh0f = (const float*)d_in[4];
    const float* Wih0b = (const float*)d_in[5];
    const float* Whh0b = (const float*)d_in[6];
    const float* bih0b = (const float*)d_in[7];
    const float* bhh0b = (const float*)d_in[8];
    const float* Wih1f = (const float*)d_in[9];
    const float* Whh1f = (const float*)d_in[10];
    const float* bih1f = (const float*)d_in[11];
    const float* bhh1f = (const float*)d_in[12];
    const float* Wih1b = (const float*)d_in[13];
    const float* Whh1b = (const float*)d_in[14];
    const float* bih1b = (const float*)d_in[15];
    const float* bhh1b = (const float*)d_in[16];
    const float* fc_w  = (const float*)d_in[17];
    const float* fc_b  = (const float*)d_in[18];
    float* out = (float*)d_out;

    float *xw0f, *xw0b, *h0, *xw1f, *h1f;
    cudaGetSymbolAddress((void**)&xw0f, g_xw0f);
    cudaGetSymbolAddress((void**)&xw0b, g_xw0b);
    cudaGetSymbolAddress((void**)&h0,   g_h0);
    cudaGetSymbolAddress((void**)&xw1f, g_xw1f);
    cudaGetSymbolAddress((void**)&h1f,  g_h1f);

    const int SMEM_G64  = 2 * 64 * (64 + 4) * 4;            // 34.8 KB
    const int SMEM_G256 = 2 * 64 * (256 + 4) * 4;           // 133 KB
    const int SMEM_S0 = (GG * 132 + 4 * HH + 1 * 4 * GG) * 4;  // ~211 KB
    const int SMEM_S1 = (GG * 132 + 2 * HH + 3 * 2 * GG) * 4;  // ~213 KB
    cudaFuncSetAttribute(gemm_xw<64>,  cudaFuncAttributeMaxDynamicSharedMemorySize, SMEM_G64);
    cudaFuncSetAttribute(gemm_xw<256>, cudaFuncAttributeMaxDynamicSharedMemorySize, SMEM_G256);
    cudaFuncSetAttribute((const void*)gru_scan<4, 2, true>,
                         cudaFuncAttributeMaxDynamicSharedMemorySize, SMEM_S0);
    cudaFuncSetAttribute((const void*)gru_scan<2, 4, false>,
                         cudaFuncAttributeMaxDynamicSharedMemorySize, SMEM_S1);

    dim3 ggrid(6, (BB * TT) / 64);

    // layer 0 input projections (f, b)
    gemm_xw<64><<<ggrid, 256, SMEM_G64>>>(x, Wih0f, bih0f, xw0f);
    gemm_xw<64><<<ggrid, 256, SMEM_G64>>>(x, Wih0b, bih0b, xw0b);

    // layer 0 scans, both directions in one launch (128 blocks, 256 thr)
    gru_scan<4, 2, true><<<dim3(BB / 4, 2), 256, SMEM_S0>>>(
        xw0f, xw0b, Whh0f, Whh0b, bhh0f, bhh0b, h0, nullptr);

    // layer 1 forward input projection + scan (final state only)
    gemm_xw<256><<<ggrid, 256, SMEM_G256>>>(h0, Wih1f, bih1f, xw1f);
    gru_scan<2, 4, false><<<dim3(BB / 2, 1), 256, SMEM_S1>>>(
        xw1f, nullptr, Whh1f, nullptr, bhh1f, nullptr, nullptr, h1f);

    // layer-1 backward one-step + ReLU + FC head
    final_kernel<<<BB, 128>>>(h0, h1f, Wih1b, bih1b, bhh1b, fc_w, fc_b, out);
}

// round 3
// speedup vs baseline: 1.3897x; 1.3897x over previous
#include <cuda_runtime.h>
#include <stdint.h>
#include <stddef.h>

#define BB 256
#define TT 512
#define HH 128
#define GG 384   /* 3*H */

typedef unsigned long long ull;

// ---------------- scratch (device globals; no allocation allowed) ----------
__device__ float g_xw0f[(size_t)BB * TT * GG];
__device__ float g_xw0b[(size_t)BB * TT * GG];
__device__ float g_h0  [(size_t)BB * TT * 2 * HH];
__device__ float g_xw1f[(size_t)BB * TT * GG];
__device__ float g_h1f [BB * HH];

// ---------------- packed f32x2 helpers -------------------------------------
__device__ __forceinline__ void ffma2(ull &d, ull a, ull b) {
    asm("fma.rn.f32x2 %0, %1, %2, %0;" : "+l"(d) : "l"(a), "l"(b));
}
__device__ __forceinline__ float hsum2(ull v) {
    float lo, hi;
    asm("mov.b64 {%0,%1}, %2;" : "=f"(lo), "=f"(hi) : "l"(v));
    return lo + hi;
}
__device__ __forceinline__ float sigf(float x)     { return 1.f / (1.f + __expf(-x)); }
__device__ __forceinline__ float tanhfast(float x) { return 2.f / (1.f + __expf(-2.f * x)) - 1.f; }

// ---------------- GEMM: C[M,384] = A[M,K] @ W[384,K]^T + bias --------------
// BM=BN=64, KT=64 double-buffered (K>64), 256 threads, 4x4 micro-tile,
// K-packed FFMA2. Panels row-major LD=68 (row stride 272B -> conflict-free
// LDS.128 across the 16 distinct rows a warp touches).
template <int K>
__global__ void __launch_bounds__(256) gemm_xw(const float* __restrict__ A,
                                               const float* __restrict__ W,
                                               const float* __restrict__ bias,
                                               float* __restrict__ C) {
    constexpr int NK = K / 64;
    constexpr int NB = (NK > 1) ? 2 : 1;
    constexpr int LD = 68;
    extern __shared__ float sm[];
    float* As = sm;                  // [NB][64*LD]
    float* Ws = sm + NB * 64 * LD;   // [NB][64*LD]
    const int tid = threadIdx.x;
    const int n0 = blockIdx.x * 64;
    const int m0 = blockIdx.y * 64;

    // stage tile ko into buffer buf
    auto stage = [&](int ko, int buf) {
        #pragma unroll
        for (int r = 0; r < 4; r++) {
            int idx = tid + r * 256;
            int row = idx >> 4, c4 = (idx & 15) * 4;
            *reinterpret_cast<float4*>(&As[buf * 64 * LD + row * LD + c4]) =
                *reinterpret_cast<const float4*>(&A[(size_t)(m0 + row) * K + ko * 64 + c4]);
            *reinterpret_cast<float4*>(&Ws[buf * 64 * LD + row * LD + c4]) =
                *reinterpret_cast<const float4*>(&W[(size_t)(n0 + row) * K + ko * 64 + c4]);
        }
    };

    stage(0, 0);
    __syncthreads();

    const int tx = tid & 15, ty = tid >> 4;
    ull acc[4][4];
    #pragma unroll
    for (int i = 0; i < 4; i++)
        #pragma unroll
        for (int j = 0; j < 4; j++) acc[i][j] = 0ULL;

    #pragma unroll
    for (int ko = 0; ko < NK; ++ko) {
        const int cur = ko & (NB - 1);
        // prefetch next tile into regs
        float4 pa[4], pw[4];
        if (ko + 1 < NK) {
            #pragma unroll
            for (int r = 0; r < 4; r++) {
                int idx = tid + r * 256;
                int row = idx >> 4, c4 = (idx & 15) * 4;
                pa[r] = *reinterpret_cast<const float4*>(&A[(size_t)(m0 + row) * K + (ko + 1) * 64 + c4]);
                pw[r] = *reinterpret_cast<const float4*>(&W[(size_t)(n0 + row) * K + (ko + 1) * 64 + c4]);
            }
        }

        #pragma unroll
        for (int kc = 0; kc < 16; ++kc) {
            ulonglong2 av[4], wv[4];
            #pragma unroll
            for (int i = 0; i < 4; i++)
                av[i] = *reinterpret_cast<const ulonglong2*>(&As[cur * 64 * LD + (ty + 16 * i) * LD + 4 * kc]);
            #pragma unroll
            for (int j = 0; j < 4; j++)
                wv[j] = *reinterpret_cast<const ulonglong2*>(&Ws[cur * 64 * LD + (tx + 16 * j) * LD + 4 * kc]);
            #pragma unroll
            for (int i = 0; i < 4; i++)
                #pragma unroll
                for (int j = 0; j < 4; j++) {
                    ffma2(acc[i][j], av[i].x, wv[j].x);
                    ffma2(acc[i][j], av[i].y, wv[j].y);
                }
        }

        if (ko + 1 < NK) {
            const int nxt = (ko + 1) & (NB - 1);
            #pragma unroll
            for (int r = 0; r < 4; r++) {
                int idx = tid + r * 256;
                int row = idx >> 4, c4 = (idx & 15) * 4;
                *reinterpret_cast<float4*>(&As[nxt * 64 * LD + row * LD + c4]) = pa[r];
                *reinterpret_cast<float4*>(&Ws[nxt * 64 * LD + row * LD + c4]) = pw[r];
            }
            __syncthreads();
        }
    }

    #pragma unroll
    for (int i = 0; i < 4; i++) {
        int m = m0 + ty + 16 * i;
        #pragma unroll
        for (int j = 0; j < 4; j++) {
            int n = n0 + tx + 16 * j;
            C[(size_t)m * GG + n] = hsum2(acc[i][j]) + bias[n];
        }
    }
}

// ---------------- GRU scan (register-stationary weights) -------------------
// 384 threads. Thread (g,u): g = tid>>7 (gate), u = tid&127 (hidden unit).
// Whh row (g*128+u) lives in 64 f32x2 registers for the whole scan.
// Per step: h read from smem via broadcast LDS.128, 256 FFMA2 from regs.
// g=1,2 partials via 4KB smem; g=0 threads apply activations (their own gate
// partial never leaves registers). 2 barriers/step.
template <int R, bool STORE_SEQ>
__global__ void __launch_bounds__(384) gru_scan(
    const float* __restrict__ xw_f, const float* __restrict__ xw_b,
    const float* __restrict__ Whh_f, const float* __restrict__ Whh_b,
    const float* __restrict__ bhh_f, const float* __restrict__ bhh_b,
    float* __restrict__ out_seq,     // [B,T,2H], column offset dir*H  (STORE_SEQ)
    float* __restrict__ out_final)   // [B,H]                          (!STORE_SEQ)
{
    __shared__ __align__(16) float hsm[R][HH];
    __shared__ float psm[2][R][HH];

    const int tid = threadIdx.x;
    const int u = tid & 127, g = tid >> 7;
    const int dir = blockIdx.y;
    const int b0 = blockIdx.x * R;

    const float* xw  = dir ? xw_b  : xw_f;
    const float* Whh = dir ? Whh_b : Whh_f;
    const float* bhh = dir ? bhh_b : bhh_f;

    // resident weights: Whh row g*128+u (512B-aligned, 32x LDG.128)
    ulonglong2 wreg[32];
    {
        const ulonglong2* wp = reinterpret_cast<const ulonglong2*>(Whh + (size_t)(g * 128 + u) * 128);
        #pragma unroll
        for (int i = 0; i < 32; i++) wreg[i] = wp[i];
    }
    for (int i = tid; i < R * HH; i += 384) (&hsm[0][0])[i] = 0.f;

    float bR = 0.f, bZ = 0.f, bN = 0.f;
    if (g == 0) { bR = bhh[u]; bZ = bhh[128 + u]; bN = bhh[256 + u]; }
    __syncthreads();

    for (int it = 0; it < TT; ++it) {
        const int t = dir ? (TT - 1 - it) : it;

        // g==0: issue xw loads early; consumed ~1.5K cycles later
        float xR[R], xZ[R], xN[R];
        if (g == 0) {
            #pragma unroll
            for (int m = 0; m < R; ++m) {
                const float* p = xw + ((size_t)(b0 + m) * TT + t) * GG;
                xR[m] = p[u]; xZ[m] = p[128 + u]; xN[m] = p[256 + u];
            }
        }

        ull acc[R];
        #pragma unroll
        for (int m = 0; m < R; ++m) acc[m] = 0ULL;

        #pragma unroll
        for (int kp = 0; kp < 32; ++kp) {
            const ulonglong2 w2 = wreg[kp];
            #pragma unroll
            for (int m = 0; m < R; ++m) {
                ulonglong2 h2 = *reinterpret_cast<const ulonglong2*>(&hsm[m][kp * 4]);
                ffma2(acc[m], w2.x, h2.x);
                ffma2(acc[m], w2.y, h2.y);
            }
        }

        if (g > 0) {
            #pragma unroll
            for (int m = 0; m < R; ++m) psm[g - 1][m][u] = hsum2(acc[m]);
        }
        __syncthreads();

        if (g == 0) {
            #pragma unroll
            for (int m = 0; m < R; ++m) {
                float aR = hsum2(acc[m]);
                float aZ = psm[0][m][u];
                float aN = psm[1][m][u];
                float r = sigf(xR[m] + aR + bR);
                float z = sigf(xZ[m] + aZ + bZ);
                float n = tanhfast(xN[m] + r * (aN + bN));
                float hn = n + z * (hsm[m][u] - n);
                hsm[m][u] = hn;
                if (STORE_SEQ)
                    out_seq[((size_t)(b0 + m) * TT + t) * (2 * HH) + dir * HH + u] = hn;
            }
        }
        __syncthreads();
    }

    if (!STORE_SEQ && g == 0) {
        #pragma unroll
        for (int m = 0; m < R; ++m)
            out_final[(b0 + m) * HH + u] = hsm[m][u];
    }
}

// ---------------- epilogue: layer-1 backward first step + ReLU + FC --------
__global__ void __launch_bounds__(128) final_kernel(
    const float* __restrict__ h0,     // [B,T,256] layer-0 concat
    const float* __restrict__ h1f,    // [B,128]   layer-1 fwd final state
    const float* __restrict__ Wih1b,  // [384][256]
    const float* __restrict__ bih, const float* __restrict__ bhh,
    const float* __restrict__ fc_w, const float* __restrict__ fc_b,
    float* __restrict__ out)          // [B,2]
{
    const int b = blockIdx.x, j = threadIdx.x;
    __shared__ __align__(16) float x1[256];
    __shared__ float red[2][128];

    const float* src = h0 + ((size_t)b * TT + (TT - 1)) * 256;
    x1[j] = src[j];
    x1[j + 128] = src[j + 128];
    __syncthreads();

    ull acc[3] = {0ULL, 0ULL, 0ULL};
    #pragma unroll 4
    for (int k = 0; k < 256; k += 4) {
        ulonglong2 xv = *reinterpret_cast<const ulonglong2*>(&x1[k]);
        #pragma unroll
        for (int g = 0; g < 3; g++) {
            ulonglong2 wv = *reinterpret_cast<const ulonglong2*>(
                &Wih1b[(size_t)(g * 128 + j) * 256 + k]);
            ffma2(acc[g], wv.x, xv.x);
            ffma2(acc[g], wv.y, xv.y);
        }
    }
    float a0 = hsum2(acc[0]) + bih[j];
    float a1 = hsum2(acc[1]) + bih[j + 128];
    float a2 = hsum2(acc[2]) + bih[j + 256];

    // reverse-scan first step at t=T-1 with h_prev = 0
    float r = sigf(a0 + bhh[j]);
    float z = sigf(a1 + bhh[j + 128]);
    float n = tanhfast(a2 + r * bhh[j + 256]);
    float hbv = (1.f - z) * n;

    float af = fmaxf(h1f[b * HH + j], 0.f);
    float ab = fmaxf(hbv, 0.f);
    red[0][j] = af * fc_w[j]       + ab * fc_w[128 + j];
    red[1][j] = af * fc_w[256 + j] + ab * fc_w[256 + 128 + j];
    __syncthreads();
    for (int s = 64; s > 0; s >>= 1) {
        if (j < s) { red[0][j] += red[0][j + s]; red[1][j] += red[1][j + s]; }
        __syncthreads();
    }
    if (j < 2) out[b * 2 + j] = red[j][0] + fc_b[j];
}

// ---------------- launch ----------------------------------------------------
extern "C" void kernel_launch(void* const* d_in, const int* in_sizes, int n_in,
                              void* d_out, int out_size) {
    const float* x     = (const float*)d_in[0];
    const float* Wih0f = (const float*)d_in[1];
    const float* Whh0f = (const float*)d_in[2];
    const float* bih0f = (const float*)d_in[3];
    const float* bhh0f = (const float*)d_in[4];
    const float* Wih0b = (const float*)d_in[5];
    const float* Whh0b = (const float*)d_in[6];
    const float* bih0b = (const float*)d_in[7];
    const float* bhh0b = (const float*)d_in[8];
    const float* Wih1f = (const float*)d_in[9];
    const float* Whh1f = (const float*)d_in[10];
    const float* bih1f = (const float*)d_in[11];
    const float* bhh1f = (const float*)d_in[12];
    const float* Wih1b = (const float*)d_in[13];
    const float* Whh1b = (const float*)d_in[14];
    const float* bih1b = (const float*)d_in[15];
    const float* bhh1b = (const float*)d_in[16];
    const float* fc_w  = (const float*)d_in[17];
    const float* fc_b  = (const float*)d_in[18];
    float* out = (float*)d_out;

    float *xw0f, *xw0b, *h0, *xw1f, *h1f;
    cudaGetSymbolAddress((void**)&xw0f, g_xw0f);
    cudaGetSymbolAddress((void**)&xw0b, g_xw0b);
    cudaGetSymbolAddress((void**)&h0,   g_h0);
    cudaGetSymbolAddress((void**)&xw1f, g_xw1f);
    cudaGetSymbolAddress((void**)&h1f,  g_h1f);

    const int SMEM_G64  = 1 * 2 * 64 * 68 * 4;   // 34816
    const int SMEM_G256 = 2 * 2 * 64 * 68 * 4;   // 69632
    cudaFuncSetAttribute(gemm_xw<64>,  cudaFuncAttributeMaxDynamicSharedMemorySize, SMEM_G64);
    cudaFuncSetAttribute(gemm_xw<256>, cudaFuncAttributeMaxDynamicSharedMemorySize, SMEM_G256);

    dim3 ggrid(6, (BB * TT) / 64);

    // layer 0 input projections (f, b)
    gemm_xw<64><<<ggrid, 256, SMEM_G64>>>(x, Wih0f, bih0f, xw0f);
    gemm_xw<64><<<ggrid, 256, SMEM_G64>>>(x, Wih0b, bih0b, xw0b);

    // layer 0 scans, both directions in one launch (128 blocks, 384 thr)
    gru_scan<4, true><<<dim3(BB / 4, 2), 384>>>(
        xw0f, xw0b, Whh0f, Whh0b, bhh0f, bhh0b, h0, nullptr);

    // layer 1 forward input projection + scan (final state only)
    gemm_xw<256><<<ggrid, 256, SMEM_G256>>>(h0, Wih1f, bih1f, xw1f);
    gru_scan<2, false><<<dim3(BB / 2, 1), 384>>>(
        xw1f, nullptr, Whh1f, nullptr, bhh1f, nullptr, nullptr, h1f);

    // layer-1 backward one-step + ReLU + FC head
    final_kernel<<<BB, 128>>>(h0, h1f, Wih1b, bih1b, bhh1b, fc_w, fc_b, out);
}